// round 8
// baseline (speedup 1.0000x reference)
#include <cuda_runtime.h>
#include <cstdint>

#define NN 50000
#define DD 128
#define EDIM 16
#define NE 800000
#define NB 49        // ceil(NN/1024)
#define CHUNK 16
#define NCHUNK (NE / CHUNK)   // 50000

// packed fp32x2 helpers (Blackwell FFMA2 path)
#define PACK2(d, lo, hi)  asm("mov.b64 %0, {%1, %2};" : "=l"(d) : "f"(lo), "f"(hi))
#define UNPACK2(lo, hi, s) asm("mov.b64 {%0, %1}, %2;" : "=f"(lo), "=f"(hi) : "l"(s))
#define FMA2(d, a, b, c)  asm("fma.rn.f32x2 %0, %1, %2, %3;" : "=l"(d) : "l"(a), "l"(b), "l"(c))
#define ADD2(d, a, b)     asm("add.rn.f32x2 %0, %1, %2;" : "=l"(d) : "l"(a), "l"(b))
#define RED4(p, v) asm volatile("red.global.add.v4.f32 [%0], {%1, %2, %3, %4};" \
                                :: "l"(p), "f"((v).x), "f"((v).y), "f"((v).z), "f"((v).w) : "memory")

// ---------------- device scratch ----------------
__device__ float g_Wef[EDIM * DD];
__device__ float g_bef[DD];
__device__ float g_W1[DD * 256];
__device__ float g_b1[256];
__device__ float g_W2[256 * DD];
__device__ float g_b2[DD];
__device__ float g_acc[(size_t)NN * DD];
__device__ float g_t[(size_t)NN * 256];
__device__ int   g_count[NN];
__device__ int   g_cursor[NN];
__device__ int   g_csum[NN];
__device__ int   g_bsum[64];
__device__ int4  g_epack4[NE];    // sorted by dst: (edge_id, src, dst, 0)

// ---------------- prep ----------------
__global__ void prep_kernel(const float* __restrict__ We1, const float* __restrict__ be1,
                            const float* __restrict__ We2, const float* __restrict__ be2,
                            const float* __restrict__ Wm1, const float* __restrict__ bm1,
                            const float* __restrict__ g1, const float* __restrict__ b1,
                            const float* __restrict__ m1, const float* __restrict__ v1,
                            const float* __restrict__ Wm2, const float* __restrict__ bm2,
                            const float* __restrict__ g2, const float* __restrict__ b2,
                            const float* __restrict__ m2, const float* __restrict__ v2) {
    int i = blockIdx.x * blockDim.x + threadIdx.x;

    if (i < NN) { g_count[i] = 0; g_cursor[i] = 0; }

    if (i < EDIM * DD) {
        int k = i / DD, d = i % DD;
        float s = 0.f;
        for (int j = 0; j < 256; j++) s += We1[k * 256 + j] * We2[j * DD + d];
        g_Wef[i] = s;
    }
    if (i < DD) {
        float s = be2[i];
        for (int j = 0; j < 256; j++) s += be1[j] * We2[j * DD + i];
        g_bef[i] = s;
    }
    if (i < DD * 256) {
        int j = i % 256;
        float a = g1[j] * rsqrtf(v1[j] + 1e-3f);
        g_W1[i] = Wm1[i] * a;
    }
    if (i < 256) {
        float a = g1[i] * rsqrtf(v1[i] + 1e-3f);
        g_b1[i] = bm1[i] * a + b1[i] - m1[i] * a;
    }
    if (i < 256 * DD) {
        int j = i % DD;
        float a = g2[j] * rsqrtf(v2[j] + 1e-3f);
        g_W2[i] = Wm2[i] * a;
    }
    if (i < DD) {
        float a = g2[i] * rsqrtf(v2[i] + 1e-3f);
        g_b2[i] = bm2[i] * a + b2[i] - m2[i] * a;
    }
}

// ---------------- CSR build ----------------
__global__ void hist_kernel(const int* __restrict__ dst) {
    int i = blockIdx.x * blockDim.x + threadIdx.x;
    if (i < NE) atomicAdd(&g_count[dst[i]], 1);
}

__global__ void scan1_kernel() {
    __shared__ int sm[1024];
    int i = blockIdx.x * 1024 + threadIdx.x;
    int v = (i < NN) ? g_count[i] : 0;
    sm[threadIdx.x] = v;
    __syncthreads();
    for (int off = 1; off < 1024; off <<= 1) {
        int add = (threadIdx.x >= off) ? sm[threadIdx.x - off] : 0;
        __syncthreads();
        sm[threadIdx.x] += add;
        __syncthreads();
    }
    if (i < NN) g_csum[i] = sm[threadIdx.x];
    if (threadIdx.x == 1023) g_bsum[blockIdx.x] = sm[1023];
}

__global__ void scan3_kernel() {
    __shared__ int off;
    if (threadIdx.x == 0) {
        int s = 0;
        for (int j = 0; j < (int)blockIdx.x; j++) s += g_bsum[j];
        off = s;
    }
    __syncthreads();
    int i = blockIdx.x * 1024 + threadIdx.x;
    if (i < NN) g_csum[i] += off;
}

__global__ void scatter_kernel(const int* __restrict__ src, const int* __restrict__ dst) {
    int i = blockIdx.x * blockDim.x + threadIdx.x;
    if (i < NE) {
        int t = dst[i];
        int beg = g_csum[t] - g_count[t];
        int pos = beg + atomicAdd(&g_cursor[t], 1);
        g_epack4[pos] = make_int4(i, src[i], t, 0);
    }
}

// ---------------- init: acc = (1+eps) * node_feat ----------------
__global__ void init_acc_kernel(const float4* __restrict__ node4, const float* __restrict__ eps) {
    int i = blockIdx.x * blockDim.x + threadIdx.x;
    const int n4 = NN * DD / 4;
    float s = 1.f + eps[0];
    float4* a4 = reinterpret_cast<float4*>(g_acc);
    if (i < n4) {
        float4 v = node4[i];
        v.x *= s; v.y *= s; v.z *= s; v.w *= s;
        a4[i] = v;
    }
}

// ---------------- load-balanced segmented accumulation ----------------
// One warp per chunk of 16 dst-sorted edges; lane owns channels 4l..4l+3.
// Same-dst runs accumulate in registers; dst change flushes via red.v4.
__global__ void __launch_bounds__(128) accum_kernel(const float* __restrict__ node,
                                                    const float* __restrict__ efeat) {
    const int lane = threadIdx.x;
    uint64_t w2[EDIM][2];
#pragma unroll
    for (int k = 0; k < EDIM; k++) {
        float4 wv = *reinterpret_cast<const float4*>(g_Wef + k * DD + lane * 4);
        PACK2(w2[k][0], wv.x, wv.y);
        PACK2(w2[k][1], wv.z, wv.w);
    }
    float4 bias = *reinterpret_cast<const float4*>(g_bef + lane * 4);
    uint64_t bias2[2];
    PACK2(bias2[0], bias.x, bias.y);
    PACK2(bias2[1], bias.z, bias.w);

    const int c = blockIdx.x * blockDim.y + threadIdx.y;
    if (c >= NCHUNK) return;
    const int base = c * CHUNK;

    int4 e = g_epack4[base];            // broadcast (uniform addr)
    int prev = e.z;
    float4 acc = make_float4(0.f, 0.f, 0.f, 0.f);

    for (int i = 0; i < CHUNK; i++) {
        int4 cur = e;
        if (i + 1 < CHUNK) e = g_epack4[base + i + 1];   // prefetch
        if (cur.z != prev) {                             // warp-uniform branch
            RED4(g_acc + (size_t)prev * DD + lane * 4, acc);
            acc = make_float4(0.f, 0.f, 0.f, 0.f);
            prev = cur.z;
        }
        float4 nf = *reinterpret_cast<const float4*>(node + (size_t)cur.y * DD + lane * 4);
        const float4* ep = reinterpret_cast<const float4*>(efeat + (size_t)cur.x * EDIM);
        float4 f0 = ep[0], f1 = ep[1], f2 = ep[2], f3 = ep[3];
        float ef[EDIM] = {f0.x, f0.y, f0.z, f0.w, f1.x, f1.y, f1.z, f1.w,
                          f2.x, f2.y, f2.z, f2.w, f3.x, f3.y, f3.z, f3.w};
        uint64_t v0, v1, n0, n1;
        PACK2(n0, nf.x, nf.y);
        PACK2(n1, nf.z, nf.w);
        ADD2(v0, bias2[0], n0);
        ADD2(v1, bias2[1], n1);
#pragma unroll
        for (int k = 0; k < EDIM; k++) {
            uint64_t e2;
            PACK2(e2, ef[k], ef[k]);
            FMA2(v0, e2, w2[k][0], v0);
            FMA2(v1, e2, w2[k][1], v1);
        }
        float x, y, z, w;
        UNPACK2(x, y, v0);
        UNPACK2(z, w, v1);
        acc.x += fmaxf(x, 0.f);
        acc.y += fmaxf(y, 0.f);
        acc.z += fmaxf(z, 0.f);
        acc.w += fmaxf(w, 0.f);
    }
    RED4(g_acc + (size_t)prev * DD + lane * 4, acc);
}

// ---------------- tiled fp32 GEMM with packed fp32x2 FMAs ----------------
__global__ void __launch_bounds__(256) gemm_kernel(const float* __restrict__ A,
                                                   const float* __restrict__ B,
                                                   const float* __restrict__ bias,
                                                   float* __restrict__ C,
                                                   int M, int N, int K, int relu) {
    __shared__ float As[8][128];
    __shared__ float Bs[8][128];

    const int tid = threadIdx.x;
    const int tx = tid % 16;
    const int ty = tid / 16;
    const int m0 = blockIdx.x * 128;
    const int n0 = blockIdx.y * 128;

    const int ar = tid >> 1;
    const int ac = (tid & 1) * 4;
    const int br = tid >> 5;
    const int bc = (tid & 31) * 4;

    uint64_t acc2[8][4];
#pragma unroll
    for (int i = 0; i < 8; i++)
#pragma unroll
        for (int j = 0; j < 4; j++) acc2[i][j] = 0ull;

    for (int k0 = 0; k0 < K; k0 += 8) {
        float4 av = make_float4(0.f, 0.f, 0.f, 0.f);
        if (m0 + ar < M)
            av = *reinterpret_cast<const float4*>(A + (size_t)(m0 + ar) * K + k0 + ac);
        As[ac + 0][ar] = av.x;
        As[ac + 1][ar] = av.y;
        As[ac + 2][ar] = av.z;
        As[ac + 3][ar] = av.w;
        float4 bv = *reinterpret_cast<const float4*>(B + (size_t)(k0 + br) * N + n0 + bc);
        *reinterpret_cast<float4*>(&Bs[br][bc]) = bv;
        __syncthreads();

#pragma unroll
        for (int kk = 0; kk < 8; kk++) {
            float4 a0 = *reinterpret_cast<const float4*>(&As[kk][ty * 8]);
            float4 a1 = *reinterpret_cast<const float4*>(&As[kk][ty * 8 + 4]);
            float4 b0 = *reinterpret_cast<const float4*>(&Bs[kk][tx * 8]);
            float4 b1 = *reinterpret_cast<const float4*>(&Bs[kk][tx * 8 + 4]);
            uint64_t b2[4];
            PACK2(b2[0], b0.x, b0.y);
            PACK2(b2[1], b0.z, b0.w);
            PACK2(b2[2], b1.x, b1.y);
            PACK2(b2[3], b1.z, b1.w);
            float a8[8] = {a0.x, a0.y, a0.z, a0.w, a1.x, a1.y, a1.z, a1.w};
#pragma unroll
            for (int i = 0; i < 8; i++) {
                uint64_t a2;
                PACK2(a2, a8[i], a8[i]);
#pragma unroll
                for (int j = 0; j < 4; j++)
                    FMA2(acc2[i][j], a2, b2[j], acc2[i][j]);
            }
        }
        __syncthreads();
    }

    float bj[8];
#pragma unroll
    for (int j = 0; j < 8; j++) bj[j] = bias[n0 + tx * 8 + j];

#pragma unroll
    for (int i = 0; i < 8; i++) {
        int row = m0 + ty * 8 + i;
        if (row < M) {
            float out[8];
#pragma unroll
            for (int j = 0; j < 4; j++) {
                float lo, hi;
                UNPACK2(lo, hi, acc2[i][j]);
                float v0 = lo + bj[2 * j];
                float v1 = hi + bj[2 * j + 1];
                out[2 * j]     = relu ? fmaxf(v0, 0.f) : v0;
                out[2 * j + 1] = relu ? fmaxf(v1, 0.f) : v1;
            }
            float4* cp = reinterpret_cast<float4*>(C + (size_t)row * N + n0 + tx * 8);
            cp[0] = make_float4(out[0], out[1], out[2], out[3]);
            cp[1] = make_float4(out[4], out[5], out[6], out[7]);
        }
    }
}

// ---------------- launch ----------------
extern "C" void kernel_launch(void* const* d_in, const int* in_sizes, int n_in,
                              void* d_out, int out_size) {
    const float* node  = (const float*)d_in[0];
    const float* efeat = (const float*)d_in[1];
    const int*   src   = (const int*)d_in[2];
    const int*   dst   = (const int*)d_in[3];
    const float* We1 = (const float*)d_in[4];
    const float* be1 = (const float*)d_in[5];
    const float* We2 = (const float*)d_in[6];
    const float* be2 = (const float*)d_in[7];
    const float* eps = (const float*)d_in[8];
    const float* Wm1 = (const float*)d_in[9];
    const float* bm1 = (const float*)d_in[10];
    const float* g1  = (const float*)d_in[11];
    const float* b1  = (const float*)d_in[12];
    const float* m1  = (const float*)d_in[13];
    const float* v1  = (const float*)d_in[14];
    const float* Wm2 = (const float*)d_in[15];
    const float* bm2 = (const float*)d_in[16];
    const float* g2  = (const float*)d_in[17];
    const float* b2  = (const float*)d_in[18];
    const float* m2  = (const float*)d_in[19];
    const float* v2  = (const float*)d_in[20];
    float* out = (float*)d_out;

    prep_kernel<<<256, 256>>>(We1, be1, We2, be2, Wm1, bm1, g1, b1, m1, v1,
                              Wm2, bm2, g2, b2, m2, v2);

    hist_kernel<<<(NE + 255) / 256, 256>>>(dst);
    scan1_kernel<<<NB, 1024>>>();
    scan3_kernel<<<NB, 1024>>>();
    scatter_kernel<<<(NE + 255) / 256, 256>>>(src, dst);

    const int n4 = NN * DD / 4;
    init_acc_kernel<<<(n4 + 255) / 256, 256>>>((const float4*)node, eps);

    // 50000 warp-chunks of 16 edges, 4 warps per 128-thread block
    accum_kernel<<<(NCHUNK + 3) / 4, dim3(32, 4)>>>(node, efeat);

    float *pacc, *pt, *pW1, *pb1, *pW2, *pb2;
    cudaGetSymbolAddress((void**)&pacc, g_acc);
    cudaGetSymbolAddress((void**)&pt,   g_t);
    cudaGetSymbolAddress((void**)&pW1,  g_W1);
    cudaGetSymbolAddress((void**)&pb1,  g_b1);
    cudaGetSymbolAddress((void**)&pW2,  g_W2);
    cudaGetSymbolAddress((void**)&pb2,  g_b2);

    gemm_kernel<<<dim3((NN + 127) / 128, 256 / 128), 256>>>(pacc, pW1, pb1, pt,
                                                            NN, 256, DD, 1);
    gemm_kernel<<<dim3((NN + 127) / 128, DD / 128), 256>>>(pt, pW2, pb2, out,
                                                           NN, DD, 256, 0);
}

// round 9
// speedup vs baseline: 1.1575x; 1.1575x over previous
#include <cuda_runtime.h>
#include <cstdint>

#define NN 50000
#define DD 128
#define EDIM 16
#define NE 800000
#define NB 49        // ceil(NN/1024)
#define CHUNK 16
#define BATCH 8
#define NCHUNK (NE / CHUNK)   // 50000

// packed fp32x2 helpers (Blackwell FFMA2 path)
#define PACK2(d, lo, hi)  asm("mov.b64 %0, {%1, %2};" : "=l"(d) : "f"(lo), "f"(hi))
#define UNPACK2(lo, hi, s) asm("mov.b64 {%0, %1}, %2;" : "=f"(lo), "=f"(hi) : "l"(s))
#define FMA2(d, a, b, c)  asm("fma.rn.f32x2 %0, %1, %2, %3;" : "=l"(d) : "l"(a), "l"(b), "l"(c))
#define ADD2(d, a, b)     asm("add.rn.f32x2 %0, %1, %2;" : "=l"(d) : "l"(a), "l"(b))
#define RED4(p, v) asm volatile("red.global.add.v4.f32 [%0], {%1, %2, %3, %4};" \
                                :: "l"(p), "f"((v).x), "f"((v).y), "f"((v).z), "f"((v).w) : "memory")
#define CPASYNC16(sm, gp) asm volatile("cp.async.ca.shared.global [%0], [%1], 16;" \
                                       :: "r"(sm), "l"(gp) : "memory")
#define CPCOMMIT() asm volatile("cp.async.commit_group;" ::: "memory")
#define CPWAIT(n)  asm volatile("cp.async.wait_group %0;" :: "n"(n) : "memory")

// ---------------- device scratch ----------------
__device__ float g_Wef[EDIM * DD];
__device__ float g_bef[DD];
__device__ float g_W1[DD * 256];
__device__ float g_b1[256];
__device__ float g_W2[256 * DD];
__device__ float g_b2[DD];
__device__ float g_acc[(size_t)NN * DD];
__device__ float g_t[(size_t)NN * 256];
__device__ int   g_count[NN];
__device__ int   g_cursor[NN];
__device__ int   g_csum[NN];
__device__ int   g_bsum[64];
__device__ int4  g_epack4[NE];    // sorted by dst: (edge_id, src, dst, 0)

// ---------------- prep + hist fused ----------------
__global__ void prep_kernel(const float* __restrict__ We1, const float* __restrict__ be1,
                            const float* __restrict__ We2, const float* __restrict__ be2,
                            const float* __restrict__ Wm1, const float* __restrict__ bm1,
                            const float* __restrict__ g1, const float* __restrict__ b1,
                            const float* __restrict__ m1, const float* __restrict__ v1,
                            const float* __restrict__ Wm2, const float* __restrict__ bm2,
                            const float* __restrict__ g2, const float* __restrict__ b2,
                            const float* __restrict__ m2, const float* __restrict__ v2,
                            const int* __restrict__ dst) {
    int i = blockIdx.x * blockDim.x + threadIdx.x;

    if (i < NN) { g_count[i] = 0; g_cursor[i] = 0; }

    if (i < EDIM * DD) {
        int k = i / DD, d = i % DD;
        float s = 0.f;
        for (int j = 0; j < 256; j++) s += We1[k * 256 + j] * We2[j * DD + d];
        g_Wef[i] = s;
    }
    if (i < DD) {
        float s = be2[i];
        for (int j = 0; j < 256; j++) s += be1[j] * We2[j * DD + i];
        g_bef[i] = s;
    }
    if (i < DD * 256) {
        int j = i % 256;
        float a = g1[j] * rsqrtf(v1[j] + 1e-3f);
        g_W1[i] = Wm1[i] * a;
    }
    if (i < 256) {
        float a = g1[i] * rsqrtf(v1[i] + 1e-3f);
        g_b1[i] = bm1[i] * a + b1[i] - m1[i] * a;
    }
    if (i < 256 * DD) {
        int j = i % DD;
        float a = g2[j] * rsqrtf(v2[j] + 1e-3f);
        g_W2[i] = Wm2[i] * a;
    }
    if (i < DD) {
        float a = g2[i] * rsqrtf(v2[i] + 1e-3f);
        g_b2[i] = bm2[i] * a + b2[i] - m2[i] * a;
    }
}

__global__ void hist_kernel(const int* __restrict__ dst) {
    int i = blockIdx.x * blockDim.x + threadIdx.x;
    if (i < NE) atomicAdd(&g_count[dst[i]], 1);
}

__global__ void scan1_kernel() {
    __shared__ int sm[1024];
    int i = blockIdx.x * 1024 + threadIdx.x;
    int v = (i < NN) ? g_count[i] : 0;
    sm[threadIdx.x] = v;
    __syncthreads();
    for (int off = 1; off < 1024; off <<= 1) {
        int add = (threadIdx.x >= off) ? sm[threadIdx.x - off] : 0;
        __syncthreads();
        sm[threadIdx.x] += add;
        __syncthreads();
    }
    if (i < NN) g_csum[i] = sm[threadIdx.x];
    if (threadIdx.x == 1023) g_bsum[blockIdx.x] = sm[1023];
}

__global__ void scan3_kernel() {
    __shared__ int off;
    if (threadIdx.x == 0) {
        int s = 0;
        for (int j = 0; j < (int)blockIdx.x; j++) s += g_bsum[j];
        off = s;
    }
    __syncthreads();
    int i = blockIdx.x * 1024 + threadIdx.x;
    if (i < NN) g_csum[i] += off;
}

__global__ void scatter_kernel(const int* __restrict__ src, const int* __restrict__ dst) {
    int i = blockIdx.x * blockDim.x + threadIdx.x;
    if (i < NE) {
        int t = dst[i];
        int beg = g_csum[t] - g_count[t];
        int pos = beg + atomicAdd(&g_cursor[t], 1);
        g_epack4[pos] = make_int4(i, src[i], t, 0);
    }
}

// ---------------- init: acc = (1+eps) * node_feat ----------------
__global__ void init_acc_kernel(const float4* __restrict__ node4, const float* __restrict__ eps) {
    int i = blockIdx.x * blockDim.x + threadIdx.x;
    const int n4 = NN * DD / 4;
    float s = 1.f + eps[0];
    float4* a4 = reinterpret_cast<float4*>(g_acc);
    if (i < n4) {
        float4 v = node4[i];
        v.x *= s; v.y *= s; v.z *= s; v.w *= s;
        a4[i] = v;
    }
}

// ---------------- cp.async staged segmented accumulation ----------------
// One warp per 16-edge dst-sorted chunk; lane owns channels 4l..4l+3.
// node[src] rows + edge features staged gmem->smem via cp.async in 2 batches
// of 8; register-run accumulation, red.v4 flush on dst change.
__global__ void __launch_bounds__(128) accum_kernel(const float* __restrict__ node,
                                                    const float* __restrict__ efeat) {
    __shared__ float s_nf[4][2][BATCH][DD];     // 32 KB
    __shared__ float s_ef[4][2][BATCH][EDIM];   // 4 KB
    __shared__ int   s_dst[4][2][BATCH];        // 256 B

    const int lane = threadIdx.x;
    const int w = threadIdx.y;

    uint64_t w2[EDIM][2];
#pragma unroll
    for (int k = 0; k < EDIM; k++) {
        float4 wv = *reinterpret_cast<const float4*>(g_Wef + k * DD + lane * 4);
        PACK2(w2[k][0], wv.x, wv.y);
        PACK2(w2[k][1], wv.z, wv.w);
    }
    float4 bias = *reinterpret_cast<const float4*>(g_bef + lane * 4);
    uint64_t bias2[2];
    PACK2(bias2[0], bias.x, bias.y);
    PACK2(bias2[1], bias.z, bias.w);

    const int c = blockIdx.x * 4 + w;
    if (c >= NCHUNK) return;
    const int base = c * CHUNK;

    // stage one batch: per edge i, lane copies its 16B slice of node[src];
    // lanes 0-3 copy the 64B edge-feature row; lane 0 stores dst.
    auto stage = [&](int buf, int ebase) {
#pragma unroll
        for (int i = 0; i < BATCH; i++) {
            int4 e = g_epack4[ebase + i];    // uniform -> broadcast
            uint32_t nf_sm = (uint32_t)__cvta_generic_to_shared(&s_nf[w][buf][i][lane * 4]);
            CPASYNC16(nf_sm, node + (size_t)e.y * DD + lane * 4);
            if (lane < 4) {
                uint32_t ef_sm = (uint32_t)__cvta_generic_to_shared(&s_ef[w][buf][i][lane * 4]);
                CPASYNC16(ef_sm, efeat + (size_t)e.x * EDIM + lane * 4);
            }
            if (lane == 0) s_dst[w][buf][i] = e.z;
        }
    };

    stage(0, base);
    CPCOMMIT();
    stage(1, base + BATCH);
    CPCOMMIT();

    float4 acc = make_float4(0.f, 0.f, 0.f, 0.f);
    int prev = -1;

#pragma unroll
    for (int b = 0; b < 2; b++) {
        if (b == 0) { CPWAIT(1); } else { CPWAIT(0); }
        __syncwarp();
        if (b == 0) prev = s_dst[w][0][0];
#pragma unroll
        for (int i = 0; i < BATCH; i++) {
            int d = s_dst[w][b][i];
            if (d != prev) {                 // warp-uniform
                RED4(g_acc + (size_t)prev * DD + lane * 4, acc);
                acc = make_float4(0.f, 0.f, 0.f, 0.f);
                prev = d;
            }
            float4 nf = *reinterpret_cast<const float4*>(&s_nf[w][b][i][lane * 4]);
            const float4* ep = reinterpret_cast<const float4*>(s_ef[w][b][i]);
            float4 f0 = ep[0], f1 = ep[1], f2 = ep[2], f3 = ep[3];  // LDS broadcast
            float ef[EDIM] = {f0.x, f0.y, f0.z, f0.w, f1.x, f1.y, f1.z, f1.w,
                              f2.x, f2.y, f2.z, f2.w, f3.x, f3.y, f3.z, f3.w};
            uint64_t v0, v1, n0, n1;
            PACK2(n0, nf.x, nf.y);
            PACK2(n1, nf.z, nf.w);
            ADD2(v0, bias2[0], n0);
            ADD2(v1, bias2[1], n1);
#pragma unroll
            for (int k = 0; k < EDIM; k++) {
                uint64_t e2;
                PACK2(e2, ef[k], ef[k]);
                FMA2(v0, e2, w2[k][0], v0);
                FMA2(v1, e2, w2[k][1], v1);
            }
            float x, y, z, wv;
            UNPACK2(x, y, v0);
            UNPACK2(z, wv, v1);
            acc.x += fmaxf(x, 0.f);
            acc.y += fmaxf(y, 0.f);
            acc.z += fmaxf(z, 0.f);
            acc.w += fmaxf(wv, 0.f);
        }
    }
    RED4(g_acc + (size_t)prev * DD + lane * 4, acc);
}

// ---------------- tiled fp32 GEMM with packed fp32x2 FMAs ----------------
__global__ void __launch_bounds__(256) gemm_kernel(const float* __restrict__ A,
                                                   const float* __restrict__ B,
                                                   const float* __restrict__ bias,
                                                   float* __restrict__ C,
                                                   int M, int N, int K, int relu) {
    __shared__ float As[8][128];
    __shared__ float Bs[8][128];

    const int tid = threadIdx.x;
    const int tx = tid % 16;
    const int ty = tid / 16;
    const int m0 = blockIdx.x * 128;
    const int n0 = blockIdx.y * 128;

    const int ar = tid >> 1;
    const int ac = (tid & 1) * 4;
    const int br = tid >> 5;
    const int bc = (tid & 31) * 4;

    uint64_t acc2[8][4];
#pragma unroll
    for (int i = 0; i < 8; i++)
#pragma unroll
        for (int j = 0; j < 4; j++) acc2[i][j] = 0ull;

    for (int k0 = 0; k0 < K; k0 += 8) {
        float4 av = make_float4(0.f, 0.f, 0.f, 0.f);
        if (m0 + ar < M)
            av = *reinterpret_cast<const float4*>(A + (size_t)(m0 + ar) * K + k0 + ac);
        As[ac + 0][ar] = av.x;
        As[ac + 1][ar] = av.y;
        As[ac + 2][ar] = av.z;
        As[ac + 3][ar] = av.w;
        float4 bv = *reinterpret_cast<const float4*>(B + (size_t)(k0 + br) * N + n0 + bc);
        *reinterpret_cast<float4*>(&Bs[br][bc]) = bv;
        __syncthreads();

#pragma unroll
        for (int kk = 0; kk < 8; kk++) {
            float4 a0 = *reinterpret_cast<const float4*>(&As[kk][ty * 8]);
            float4 a1 = *reinterpret_cast<const float4*>(&As[kk][ty * 8 + 4]);
            float4 b0 = *reinterpret_cast<const float4*>(&Bs[kk][tx * 8]);
            float4 b1 = *reinterpret_cast<const float4*>(&Bs[kk][tx * 8 + 4]);
            uint64_t b2[4];
            PACK2(b2[0], b0.x, b0.y);
            PACK2(b2[1], b0.z, b0.w);
            PACK2(b2[2], b1.x, b1.y);
            PACK2(b2[3], b1.z, b1.w);
            float a8[8] = {a0.x, a0.y, a0.z, a0.w, a1.x, a1.y, a1.z, a1.w};
#pragma unroll
            for (int i = 0; i < 8; i++) {
                uint64_t a2;
                PACK2(a2, a8[i], a8[i]);
#pragma unroll
                for (int j = 0; j < 4; j++)
                    FMA2(acc2[i][j], a2, b2[j], acc2[i][j]);
            }
        }
        __syncthreads();
    }

    float bj[8];
#pragma unroll
    for (int j = 0; j < 8; j++) bj[j] = bias[n0 + tx * 8 + j];

#pragma unroll
    for (int i = 0; i < 8; i++) {
        int row = m0 + ty * 8 + i;
        if (row < M) {
            float out[8];
#pragma unroll
            for (int j = 0; j < 4; j++) {
                float lo, hi;
                UNPACK2(lo, hi, acc2[i][j]);
                float v0 = lo + bj[2 * j];
                float v1 = hi + bj[2 * j + 1];
                out[2 * j]     = relu ? fmaxf(v0, 0.f) : v0;
                out[2 * j + 1] = relu ? fmaxf(v1, 0.f) : v1;
            }
            float4* cp = reinterpret_cast<float4*>(C + (size_t)row * N + n0 + tx * 8);
            cp[0] = make_float4(out[0], out[1], out[2], out[3]);
            cp[1] = make_float4(out[4], out[5], out[6], out[7]);
        }
    }
}

// ---------------- launch ----------------
extern "C" void kernel_launch(void* const* d_in, const int* in_sizes, int n_in,
                              void* d_out, int out_size) {
    const float* node  = (const float*)d_in[0];
    const float* efeat = (const float*)d_in[1];
    const int*   src   = (const int*)d_in[2];
    const int*   dst   = (const int*)d_in[3];
    const float* We1 = (const float*)d_in[4];
    const float* be1 = (const float*)d_in[5];
    const float* We2 = (const float*)d_in[6];
    const float* be2 = (const float*)d_in[7];
    const float* eps = (const float*)d_in[8];
    const float* Wm1 = (const float*)d_in[9];
    const float* bm1 = (const float*)d_in[10];
    const float* g1  = (const float*)d_in[11];
    const float* b1  = (const float*)d_in[12];
    const float* m1  = (const float*)d_in[13];
    const float* v1  = (const float*)d_in[14];
    const float* Wm2 = (const float*)d_in[15];
    const float* bm2 = (const float*)d_in[16];
    const float* g2  = (const float*)d_in[17];
    const float* b2  = (const float*)d_in[18];
    const float* m2  = (const float*)d_in[19];
    const float* v2  = (const float*)d_in[20];
    float* out = (float*)d_out;

    prep_kernel<<<256, 256>>>(We1, be1, We2, be2, Wm1, bm1, g1, b1, m1, v1,
                              Wm2, bm2, g2, b2, m2, v2, dst);
    hist_kernel<<<(NE + 255) / 256, 256>>>(dst);
    scan1_kernel<<<NB, 1024>>>();
    scan3_kernel<<<NB, 1024>>>();
    scatter_kernel<<<(NE + 255) / 256, 256>>>(src, dst);

    const int n4 = NN * DD / 4;
    init_acc_kernel<<<(n4 + 255) / 256, 256>>>((const float4*)node, eps);

    accum_kernel<<<(NCHUNK + 3) / 4, dim3(32, 4)>>>(node, efeat);

    float *pacc, *pt, *pW1, *pb1, *pW2, *pb2;
    cudaGetSymbolAddress((void**)&pacc, g_acc);
    cudaGetSymbolAddress((void**)&pt,   g_t);
    cudaGetSymbolAddress((void**)&pW1,  g_W1);
    cudaGetSymbolAddress((void**)&pb1,  g_b1);
    cudaGetSymbolAddress((void**)&pW2,  g_W2);
    cudaGetSymbolAddress((void**)&pb2,  g_b2);

    gemm_kernel<<<dim3((NN + 127) / 128, 256 / 128), 256>>>(pacc, pW1, pb1, pt,
                                                            NN, 256, DD, 1);
    gemm_kernel<<<dim3((NN + 127) / 128, DD / 128), 256>>>(pt, pW2, pb2, out,
                                                           NN, DD, 256, 0);
}